// round 9
// baseline (speedup 1.0000x reference)
#include <cuda_runtime.h>
#include <math.h>
#include <stdint.h>

// Problem constants
#define V_ 50000
#define E_ 300
#define T_ 512
#define U_ 256
#define G_ 768      // 3*U
#define B_ 64
#define C_ 20
#define M_ (B_*T_)  // 32768

// ---------------- static device scratch ----------------
__device__ float g_xw[2][(size_t)M_ * G_];     // input projections per direction
__device__ float g_h1[(size_t)M_ * 2 * U_];    // layer1 output [B,T,512]
__device__ float g_h2[B_][2 * U_];             // final states

__device__ __forceinline__ uint32_t smem_u32(const void* p) {
    uint32_t a;
    asm("{ .reg .u64 t; cvta.to.shared.u64 t, %1; cvt.u32.u64 %0, t; }" : "=r"(a) : "l"(p));
    return a;
}
__device__ __forceinline__ void mma_tf32_16n8k8(float* c, const uint32_t* a, const uint32_t* b) {
    asm volatile(
        "mma.sync.aligned.m16n8k8.row.col.f32.tf32.tf32.f32 "
        "{%0,%1,%2,%3}, {%4,%5,%6,%7}, {%8,%9}, {%0,%1,%2,%3};"
        : "+f"(c[0]), "+f"(c[1]), "+f"(c[2]), "+f"(c[3])
        : "r"(a[0]), "r"(a[1]), "r"(a[2]), "r"(a[3]), "r"(b[0]), "r"(b[1]));
}
#define CP_COMMIT() asm volatile("cp.async.commit_group;" ::: "memory")
#define CP_WAIT(n)  asm volatile("cp.async.wait_group %0;" :: "n"(n) : "memory")

// ---------------- tf32 mma.sync GEMM, cp.async double-buffered ----------------
// C[M,768] = A[M,Kreal] @ W[Kreal,768] + bias ; A rows optionally indirect (emb[x]).
// CTA tile 128x128, BK=32, 256 threads = 8 warps (4 M x 2 N), warp tile 32x64.
#define SA_ 36
#define SB_ 136
#define A_FLOATS (128 * SA_)
#define B_FLOATS (32 * SB_)
#define BUF_FLOATS (A_FLOATS + B_FLOATS)
#define GEMM_SMEM (2 * BUF_FLOATS * 4)

__device__ __forceinline__ void stage_tile(
    uint32_t sa, uint32_t sb, const float* __restrict__ arow_p,
    const float* __restrict__ W, int n0, int k0, int Kreal, int tid)
{
    // A: this thread stages half a row (4 x 16B)
    {
        int arow  = tid >> 1;
        int aseg0 = (tid & 1) * 4;
#pragma unroll
        for (int q = 0; q < 4; q++) {
            int col = k0 + (aseg0 + q) * 4;
            int szf = Kreal - col; szf = szf < 0 ? 0 : (szf > 4 ? 4 : szf);
            int sz = szf * 4;
            const float* src = arow_p + (sz ? col : 0);
            uint32_t dst = sa + (uint32_t)(arow * SA_ + (aseg0 + q) * 4) * 4u;
            asm volatile("cp.async.cg.shared.global [%0], [%1], 16, %2;"
                         :: "r"(dst), "l"(src), "r"(sz) : "memory");
        }
    }
    // B: 32 k-rows x 128 cols
    {
        int krow  = tid >> 3;
        int bseg0 = (tid & 7) * 4;
        int kr = k0 + krow;
        int sz = (kr < Kreal) ? 16 : 0;
        const float* brow_p = W + (size_t)(sz ? kr : 0) * G_ + n0;
#pragma unroll
        for (int q = 0; q < 4; q++) {
            uint32_t dst = sb + (uint32_t)(krow * SB_ + (bseg0 + q) * 4) * 4u;
            asm volatile("cp.async.cg.shared.global [%0], [%1], 16, %2;"
                         :: "r"(dst), "l"(brow_p + (bseg0 + q) * 4), "r"(sz) : "memory");
        }
    }
}

__global__ void __launch_bounds__(256, 2) mma_gemm_k(
    const float* __restrict__ A, const float* __restrict__ W,
    const float* __restrict__ bias, float* __restrict__ Cc,
    int Kreal, const int* __restrict__ xidx)
{
    extern __shared__ float smf[];
    const uint32_t sbase = smem_u32(smf);

    const int tid  = threadIdx.x;
    const int wid  = tid >> 5;
    const int lane = tid & 31;
    const int lq   = lane & 3;
    const int gid  = lane >> 2;
    const int m0 = blockIdx.y * 128;
    const int n0 = blockIdx.x * 128;
    const int m0w = (wid & 3) * 32;
    const int n0w = (wid >> 2) * 64;

    // A row base for this thread's staging role (constant across k-tiles)
    const int arow = tid >> 1;
    const int ridx = xidx ? __ldg(&xidx[m0 + arow]) : (m0 + arow);
    const float* arow_p = A + (size_t)ridx * Kreal;

    float2 bv[8];
#pragma unroll
    for (int nt = 0; nt < 8; nt++)
        bv[nt] = *(const float2*)&bias[n0 + n0w + nt * 8 + lq * 2];

    float cfr[2][8][4];
#pragma unroll
    for (int mt = 0; mt < 2; mt++)
#pragma unroll
        for (int nt = 0; nt < 8; nt++)
#pragma unroll
            for (int j = 0; j < 4; j++) cfr[mt][nt][j] = 0.f;

    const int KT = (Kreal + 31) >> 5;

    stage_tile(sbase, sbase + A_FLOATS * 4u, arow_p, W, n0, 0, Kreal, tid);
    CP_COMMIT();

    for (int kt = 0; kt < KT; kt++) {
        const int cur = kt & 1;
        if (kt + 1 < KT) {
            uint32_t nb = sbase + (uint32_t)(((kt + 1) & 1) * BUF_FLOATS) * 4u;
            stage_tile(nb, nb + A_FLOATS * 4u, arow_p, W, n0, (kt + 1) << 5, Kreal, tid);
            CP_COMMIT();
            CP_WAIT(1);
        } else {
            CP_WAIT(0);
        }
        __syncthreads();

        const float* As_ = smf + cur * BUF_FLOATS;
        const float* Bs_ = As_ + A_FLOATS;

#pragma unroll
        for (int ks = 0; ks < 4; ks++) {
            const int kb = ks * 8;
            uint32_t af[2][4], bf[8][2];
#pragma unroll
            for (int mt = 0; mt < 2; mt++) {
                const float* ap = As_ + (m0w + mt * 16 + gid) * SA_ + kb + lq;
                af[mt][0] = __float_as_uint(ap[0]);
                af[mt][1] = __float_as_uint(ap[8 * SA_]);
                af[mt][2] = __float_as_uint(ap[4]);
                af[mt][3] = __float_as_uint(ap[8 * SA_ + 4]);
            }
#pragma unroll
            for (int nt = 0; nt < 8; nt++) {
                const float* bp = Bs_ + (kb + lq) * SB_ + n0w + nt * 8 + gid;
                bf[nt][0] = __float_as_uint(bp[0]);
                bf[nt][1] = __float_as_uint(bp[4 * SB_]);
            }
#pragma unroll
            for (int mt = 0; mt < 2; mt++)
#pragma unroll
                for (int nt = 0; nt < 8; nt++)
                    mma_tf32_16n8k8(cfr[mt][nt], af[mt], bf[nt]);
        }
        __syncthreads();
    }

#pragma unroll
    for (int mt = 0; mt < 2; mt++) {
        int row = m0 + m0w + mt * 16 + gid;
#pragma unroll
        for (int nt = 0; nt < 8; nt++) {
            int col = n0 + n0w + nt * 8 + lq * 2;
            float2 v0, v1;
            v0.x = cfr[mt][nt][0] + bv[nt].x;
            v0.y = cfr[mt][nt][1] + bv[nt].y;
            v1.x = cfr[mt][nt][2] + bv[nt].x;
            v1.y = cfr[mt][nt][3] + bv[nt].y;
            *(float2*)&Cc[(size_t)row * G_ + col] = v0;
            *(float2*)&Cc[(size_t)(row + 8) * G_ + col] = v1;
        }
    }
}

// ---------------- persistent bidirectional GRU scan — cluster version ----------------
// grid = 128 CTAs, cluster = 8 CTAs = one (dir, batch-block) group (ublk = cluster rank).
// Each CTA: 8 batches x 32 units; weights (96KB) in smem; h exchanged by DSMEM
// push (st.shared::cluster) into every peer's double-buffered hs[2][256][8];
// one barrier.cluster per step (replaces L2 atomic barrier + global h round-trip).
#define SC_WK   (256*96)          // 24576
#define SC_HSB  2048              // one hs buffer: 256 k x 8 b
#define SC_SMEM_FLOATS (SC_WK + 2*SC_HSB + 2*8*96)
__global__ void __launch_bounds__(384, 1) scan_k(
    const float* __restrict__ rkf, const float* __restrict__ rbf,
    const float* __restrict__ rkb, const float* __restrict__ rbb,
    int layer)
{
    extern __shared__ float sm[];
    float* wk   = sm;                        // [256][96]
    float* hs   = sm + SC_WK;                // [2][256][8]
    float* part = sm + SC_WK + 2 * SC_HSB;   // [2][8][96]

    const int cta  = blockIdx.x;
    const int dir  = cta >> 6;
    const int bblk = (cta >> 3) & 7;
    const int ublk = cta & 7;                // cluster rank
    const int b0 = bblk * 8, u0 = ublk * 32;
    const int tid = threadIdx.x;

    const float* rk = dir ? rkb : rkf;
    const float* rb = dir ? rbb : rbf;
    const float* xw = g_xw[dir];

    // remote hs base addresses (one per cluster rank), hoisted
    const uint32_t hs_l = smem_u32(hs);
    uint32_t rmt[8];
#pragma unroll
    for (int r = 0; r < 8; r++)
        asm("mapa.shared::cluster.u32 %0, %1, %2;" : "=r"(rmt[r]) : "r"(hs_l), "r"(r));

    // load recurrent-weight slice: wk[k][g*32+uu] = rk[k*768 + g*256 + u0+uu]
    for (int i = tid; i < SC_WK; i += 384) {
        int k = i / 96, col = i % 96;
        int g = col >> 5, uu = col & 31;
        wk[i] = rk[(size_t)k * G_ + g * U_ + u0 + uu];
    }
    // zero hs buffer 1 (h_{-1} source for step 0)
    for (int i = tid; i < SC_HSB; i += 384) hs[SC_HSB + i] = 0.f;

    const int kh   = tid / 192;              // dot roles
    const int r2   = tid % 192;
    const int bg   = r2 / 96;
    const int colT = r2 % 96;
    const int gb  = tid >> 5;                // gate roles (tid < 256)
    const int guu = tid & 31;
    float bz = 0.f, br = 0.f, bh = 0.f;
    if (tid < 256) {
        bz = rb[u0 + guu];
        br = rb[U_ + u0 + guu];
        bh = rb[2 * U_ + u0 + guu];
    }
    __syncthreads();

    for (int s = 0; s < T_; s++) {
        const int t = dir ? (T_ - 1 - s) : s;
        const float* hprev = hs + ((s + 1) & 1) * SC_HSB;   // buffer (s-1)&1

        // prefetch xw for gate phase
        float xz = 0.f, xr = 0.f, xh = 0.f;
        if (tid < 256) {
            const float* xwp = xw + ((size_t)(b0 + gb) * T_ + t) * G_;
            xz = __ldg(xwp + u0 + guu);
            xr = __ldg(xwp + U_ + u0 + guu);
            xh = __ldg(xwp + 2 * U_ + u0 + guu);
        }

        // dot: partial inner products over this k-half
        {
            float a0 = 0.f, a1 = 0.f, a2 = 0.f, a3 = 0.f;
            const float* wp = wk + (kh * 128) * 96 + colT;
            const float* hp = hprev + (kh * 128) * 8 + bg * 4;
#pragma unroll 8
            for (int k = 0; k < 128; k++) {
                float  w  = wp[k * 96];
                float4 h4 = *(const float4*)(hp + k * 8);
                a0 = fmaf(h4.x, w, a0);
                a1 = fmaf(h4.y, w, a1);
                a2 = fmaf(h4.z, w, a2);
                a3 = fmaf(h4.w, w, a3);
            }
            part[(kh * 8 + bg * 4 + 0) * 96 + colT] = a0;
            part[(kh * 8 + bg * 4 + 1) * 96 + colT] = a1;
            part[(kh * 8 + bg * 4 + 2) * 96 + colT] = a2;
            part[(kh * 8 + bg * 4 + 3) * 96 + colT] = a3;
        }
        __syncthreads();

        // gates + DSMEM push of h_t to all cluster peers
        if (tid < 256) {
            float az = bz + part[(0 * 8 + gb) * 96 + guu]      + part[(1 * 8 + gb) * 96 + guu];
            float ar = br + part[(0 * 8 + gb) * 96 + 32 + guu] + part[(1 * 8 + gb) * 96 + 32 + guu];
            float ah = bh + part[(0 * 8 + gb) * 96 + 64 + guu] + part[(1 * 8 + gb) * 96 + 64 + guu];
            float hp0 = hprev[(u0 + guu) * 8 + gb];
            float z  = 1.f / (1.f + expf(-(xz + az)));
            float rg = 1.f / (1.f + expf(-(xr + ar)));
            float hh = tanhf(xh + rg * ah);
            float hn = z * hp0 + (1.f - z) * hh;

            if (layer == 1)
                __stcg(&g_h1[((size_t)(b0 + gb) * T_ + t) * (2 * U_) + dir * U_ + u0 + guu], hn);
            else if (s == T_ - 1)
                g_h2[b0 + gb][dir * U_ + u0 + guu] = hn;

            if (s != T_ - 1) {
                const uint32_t off = (uint32_t)(((s & 1) * SC_HSB + (u0 + guu) * 8 + gb) * 4);
#pragma unroll
                for (int r = 0; r < 8; r++)
                    asm volatile("st.shared::cluster.f32 [%0], %1;"
                                 :: "r"(rmt[r] + off), "f"(hn) : "memory");
            }
        }

        if (s != T_ - 1) {
            asm volatile("barrier.cluster.arrive.aligned;" ::: "memory");
            asm volatile("barrier.cluster.wait.aligned;"   ::: "memory");
        }
    }
}

// ---------------- head: softmax(h2 @ wout + bout) ----------------
__global__ void head_k(const float* __restrict__ wout, const float* __restrict__ bout,
                       float* __restrict__ out)
{
    const int b = blockIdx.x, lane = threadIdx.x;
    float acc = 0.f;
    if (lane < C_) {
        acc = bout[lane];
        for (int k = 0; k < 2 * U_; k++)
            acc = fmaf(g_h2[b][k], wout[k * C_ + lane], acc);
    }
    float v = (lane < C_) ? acc : -INFINITY;
    for (int o = 16; o; o >>= 1) v = fmaxf(v, __shfl_xor_sync(0xffffffffu, v, o));
    float e = (lane < C_) ? expf(acc - v) : 0.f;
    float ssum = e;
    for (int o = 16; o; o >>= 1) ssum += __shfl_xor_sync(0xffffffffu, ssum, o);
    if (lane < C_) out[b * C_ + lane] = e / ssum;
}

// ---------------- launch ----------------
static void launch_scan(const float* rk_f, const float* rb_f,
                        const float* rk_b, const float* rb_b, int layer, int smem)
{
    cudaLaunchConfig_t cfg = {};
    cfg.gridDim  = dim3(128, 1, 1);
    cfg.blockDim = dim3(384, 1, 1);
    cfg.dynamicSmemBytes = (size_t)smem;
    cfg.stream = 0;
    cudaLaunchAttribute attr[1];
    attr[0].id = cudaLaunchAttributeClusterDimension;
    attr[0].val.clusterDim.x = 8;
    attr[0].val.clusterDim.y = 1;
    attr[0].val.clusterDim.z = 1;
    cfg.attrs = attr;
    cfg.numAttrs = 1;
    cudaLaunchKernelEx(&cfg, scan_k, rk_f, rb_f, rk_b, rb_b, layer);
}

extern "C" void kernel_launch(void* const* d_in, const int* in_sizes, int n_in,
                              void* d_out, int out_size)
{
    const int*   x    = (const int*)  d_in[0];
    const float* emb  = (const float*)d_in[1];
    const float* k1f  = (const float*)d_in[2];
    const float* rk1f = (const float*)d_in[3];
    const float* b1f  = (const float*)d_in[4];
    const float* k1b  = (const float*)d_in[5];
    const float* rk1b = (const float*)d_in[6];
    const float* b1b  = (const float*)d_in[7];
    const float* k2f  = (const float*)d_in[8];
    const float* rk2f = (const float*)d_in[9];
    const float* b2f  = (const float*)d_in[10];
    const float* k2b  = (const float*)d_in[11];
    const float* rk2b = (const float*)d_in[12];
    const float* b2b  = (const float*)d_in[13];
    const float* wout = (const float*)d_in[14];
    const float* bout = (const float*)d_in[15];
    float* out = (float*)d_out;

    float *pxw0, *pxw1, *ph1;
    cudaGetSymbolAddress((void**)&pxw0, g_xw);
    pxw1 = pxw0 + (size_t)M_ * G_;
    cudaGetSymbolAddress((void**)&ph1,  g_h1);

    const int scan_smem = SC_SMEM_FLOATS * (int)sizeof(float);   // ~118 KB
    cudaFuncSetAttribute(scan_k,     cudaFuncAttributeMaxDynamicSharedMemorySize, scan_smem);
    cudaFuncSetAttribute(mma_gemm_k, cudaFuncAttributeMaxDynamicSharedMemorySize, GEMM_SMEM);

    dim3 gg(G_ / 128, M_ / 128);   // (6, 256)

    // 1) layer-1 input projections, gather fused (A rows = emb[x[row]])
    mma_gemm_k<<<gg, 256, GEMM_SMEM>>>(emb, k1f, b1f, pxw0, E_, x);
    mma_gemm_k<<<gg, 256, GEMM_SMEM>>>(emb, k1b, b1b, pxw1, E_, x);

    // 2) layer-1 bidirectional scan -> g_h1   (clustered)
    launch_scan(rk1f, b1f + G_, rk1b, b1b + G_, 1, scan_smem);

    // 3) layer-2 input projections
    mma_gemm_k<<<gg, 256, GEMM_SMEM>>>(ph1, k2f, b2f, pxw0, 2 * U_, (const int*)nullptr);
    mma_gemm_k<<<gg, 256, GEMM_SMEM>>>(ph1, k2b, b2b, pxw1, 2 * U_, (const int*)nullptr);

    // 4) layer-2 bidirectional scan -> g_h2   (clustered)
    launch_scan(rk2f, b2f + G_, rk2b, b2b + G_, 2, scan_smem);

    // 5) output head
    head_k<<<B_, 32>>>(wout, bout, out);
}

// round 10
// speedup vs baseline: 1.7370x; 1.7370x over previous
#include <cuda_runtime.h>
#include <math.h>
#include <stdint.h>

// Problem constants
#define V_ 50000
#define E_ 300
#define T_ 512
#define U_ 256
#define G_ 768      // 3*U
#define B_ 64
#define C_ 20
#define M_ (B_*T_)  // 32768

// ---------------- static device scratch ----------------
__device__ float g_xw[2][(size_t)M_ * G_];     // input projections per direction
__device__ float g_h1[(size_t)M_ * 2 * U_];    // layer1 output [B,T,512]
__device__ float g_hs2[2][2][B_][U_];          // layer2 h double buffer [parity][dir][B][U]
__device__ float g_h2[B_][2 * U_];             // final states
// one counter per (dir, bblk) group, padded to a private 128B line (no false sharing)
__device__ unsigned g_cnt1[16 * 32];
__device__ unsigned g_cnt2[16 * 32];

__device__ __forceinline__ uint32_t smem_u32(const void* p) {
    uint32_t a;
    asm("{ .reg .u64 t; cvta.to.shared.u64 t, %1; cvt.u32.u64 %0, t; }" : "=r"(a) : "l"(p));
    return a;
}
__device__ __forceinline__ void mma_tf32_16n8k8(float* c, const uint32_t* a, const uint32_t* b) {
    asm volatile(
        "mma.sync.aligned.m16n8k8.row.col.f32.tf32.tf32.f32 "
        "{%0,%1,%2,%3}, {%4,%5,%6,%7}, {%8,%9}, {%0,%1,%2,%3};"
        : "+f"(c[0]), "+f"(c[1]), "+f"(c[2]), "+f"(c[3])
        : "r"(a[0]), "r"(a[1]), "r"(a[2]), "r"(a[3]), "r"(b[0]), "r"(b[1]));
}
#define CP_COMMIT() asm volatile("cp.async.commit_group;" ::: "memory")
#define CP_WAIT(n)  asm volatile("cp.async.wait_group %0;" :: "n"(n) : "memory")

// ---------------- init: reset barrier counters ----------------
__global__ void init_k() {
    if (threadIdx.x < 16) {
        g_cnt1[threadIdx.x * 32] = 0u;
        g_cnt2[threadIdx.x * 32] = 0u;
    }
}

// ---------------- tf32 mma.sync GEMM, cp.async double-buffered ----------------
// C[M,768] = A[M,Kreal] @ W[Kreal,768] + bias ; A rows optionally indirect (emb[x]).
// CTA tile 128x128, BK=32, 256 threads = 8 warps (4 M x 2 N), warp tile 32x64.
#define SA_ 36
#define SB_ 136
#define A_FLOATS (128 * SA_)
#define B_FLOATS (32 * SB_)
#define BUF_FLOATS (A_FLOATS + B_FLOATS)
#define GEMM_SMEM (2 * BUF_FLOATS * 4)

__device__ __forceinline__ void stage_tile(
    uint32_t sa, uint32_t sb, const float* __restrict__ arow_p,
    const float* __restrict__ W, int n0, int k0, int Kreal, int tid)
{
    // A: this thread stages half a row (4 x 16B)
    {
        int arow  = tid >> 1;
        int aseg0 = (tid & 1) * 4;
#pragma unroll
        for (int q = 0; q < 4; q++) {
            int col = k0 + (aseg0 + q) * 4;
            int szf = Kreal - col; szf = szf < 0 ? 0 : (szf > 4 ? 4 : szf);
            int sz = szf * 4;
            const float* src = arow_p + (sz ? col : 0);
            uint32_t dst = sa + (uint32_t)(arow * SA_ + (aseg0 + q) * 4) * 4u;
            asm volatile("cp.async.cg.shared.global [%0], [%1], 16, %2;"
                         :: "r"(dst), "l"(src), "r"(sz) : "memory");
        }
    }
    // B: 32 k-rows x 128 cols
    {
        int krow  = tid >> 3;
        int bseg0 = (tid & 7) * 4;
        int kr = k0 + krow;
        int sz = (kr < Kreal) ? 16 : 0;
        const float* brow_p = W + (size_t)(sz ? kr : 0) * G_ + n0;
#pragma unroll
        for (int q = 0; q < 4; q++) {
            uint32_t dst = sb + (uint32_t)(krow * SB_ + (bseg0 + q) * 4) * 4u;
            asm volatile("cp.async.cg.shared.global [%0], [%1], 16, %2;"
                         :: "r"(dst), "l"(brow_p + (bseg0 + q) * 4), "r"(sz) : "memory");
        }
    }
}

__global__ void __launch_bounds__(256, 2) mma_gemm_k(
    const float* __restrict__ A, const float* __restrict__ W,
    const float* __restrict__ bias, float* __restrict__ Cc,
    int Kreal, const int* __restrict__ xidx)
{
    extern __shared__ float smf[];
    const uint32_t sbase = smem_u32(smf);

    const int tid  = threadIdx.x;
    const int wid  = tid >> 5;
    const int lane = tid & 31;
    const int lq   = lane & 3;
    const int gid  = lane >> 2;
    const int m0 = blockIdx.y * 128;
    const int n0 = blockIdx.x * 128;
    const int m0w = (wid & 3) * 32;
    const int n0w = (wid >> 2) * 64;

    const int arow = tid >> 1;
    const int ridx = xidx ? __ldg(&xidx[m0 + arow]) : (m0 + arow);
    const float* arow_p = A + (size_t)ridx * Kreal;

    float2 bv[8];
#pragma unroll
    for (int nt = 0; nt < 8; nt++)
        bv[nt] = *(const float2*)&bias[n0 + n0w + nt * 8 + lq * 2];

    float cfr[2][8][4];
#pragma unroll
    for (int mt = 0; mt < 2; mt++)
#pragma unroll
        for (int nt = 0; nt < 8; nt++)
#pragma unroll
            for (int j = 0; j < 4; j++) cfr[mt][nt][j] = 0.f;

    const int KT = (Kreal + 31) >> 5;

    stage_tile(sbase, sbase + A_FLOATS * 4u, arow_p, W, n0, 0, Kreal, tid);
    CP_COMMIT();

    for (int kt = 0; kt < KT; kt++) {
        const int cur = kt & 1;
        if (kt + 1 < KT) {
            uint32_t nb = sbase + (uint32_t)(((kt + 1) & 1) * BUF_FLOATS) * 4u;
            stage_tile(nb, nb + A_FLOATS * 4u, arow_p, W, n0, (kt + 1) << 5, Kreal, tid);
            CP_COMMIT();
            CP_WAIT(1);
        } else {
            CP_WAIT(0);
        }
        __syncthreads();

        const float* As_ = smf + cur * BUF_FLOATS;
        const float* Bs_ = As_ + A_FLOATS;

#pragma unroll
        for (int ks = 0; ks < 4; ks++) {
            const int kb = ks * 8;
            uint32_t af[2][4], bf[8][2];
#pragma unroll
            for (int mt = 0; mt < 2; mt++) {
                const float* ap = As_ + (m0w + mt * 16 + gid) * SA_ + kb + lq;
                af[mt][0] = __float_as_uint(ap[0]);
                af[mt][1] = __float_as_uint(ap[8 * SA_]);
                af[mt][2] = __float_as_uint(ap[4]);
                af[mt][3] = __float_as_uint(ap[8 * SA_ + 4]);
            }
#pragma unroll
            for (int nt = 0; nt < 8; nt++) {
                const float* bp = Bs_ + (kb + lq) * SB_ + n0w + nt * 8 + gid;
                bf[nt][0] = __float_as_uint(bp[0]);
                bf[nt][1] = __float_as_uint(bp[4 * SB_]);
            }
#pragma unroll
            for (int mt = 0; mt < 2; mt++)
#pragma unroll
                for (int nt = 0; nt < 8; nt++)
                    mma_tf32_16n8k8(cfr[mt][nt], af[mt], bf[nt]);
        }
        __syncthreads();
    }

#pragma unroll
    for (int mt = 0; mt < 2; mt++) {
        int row = m0 + m0w + mt * 16 + gid;
#pragma unroll
        for (int nt = 0; nt < 8; nt++) {
            int col = n0 + n0w + nt * 8 + lq * 2;
            float2 v0, v1;
            v0.x = cfr[mt][nt][0] + bv[nt].x;
            v0.y = cfr[mt][nt][1] + bv[nt].y;
            v1.x = cfr[mt][nt][2] + bv[nt].x;
            v1.y = cfr[mt][nt][3] + bv[nt].y;
            *(float2*)&Cc[(size_t)row * G_ + col] = v0;
            *(float2*)&Cc[(size_t)(row + 8) * G_ + col] = v1;
        }
    }
}

// ---------------- persistent bidirectional GRU scan ----------------
// grid = 128 CTAs: dir(2) x batch-block(8, 8 batches) x unit-block(8, 32 units)
// block = 384 threads. Weights in smem; h exchanged via L2; per-group L2 barrier
// on a PRIVATE 128B cacheline per group (no cross-group false sharing).
#define SC_SMEM_FLOATS (256*96 + 256*8 + 2*8*96)
__global__ void __launch_bounds__(384, 1) scan_k(
    const float* __restrict__ rkf, const float* __restrict__ rbf,
    const float* __restrict__ rkb, const float* __restrict__ rbb,
    unsigned* __restrict__ cnt, int layer)
{
    extern __shared__ float sm[];
    float* wk   = sm;                      // [256][96]
    float* hs   = sm + 256 * 96;           // [256][8]
    float* part = hs + 256 * 8;            // [2][8][96]

    const int cta  = blockIdx.x;
    const int dir  = cta >> 6;
    const int bblk = (cta >> 3) & 7;
    const int ublk = cta & 7;
    const int b0 = bblk * 8, u0 = ublk * 32;
    const int tid = threadIdx.x;

    const float* rk = dir ? rkb : rkf;
    const float* rb = dir ? rbb : rbf;
    const float* xw = g_xw[dir];

    for (int i = tid; i < 256 * 96; i += 384) {
        int k = i / 96, col = i % 96;
        int g = col >> 5, uu = col & 31;
        wk[i] = rk[(size_t)k * G_ + g * U_ + u0 + uu];
    }

    const int kh   = tid / 192;
    const int r2   = tid % 192;
    const int bg   = r2 / 96;
    const int colT = r2 % 96;
    const int gb  = tid >> 5;
    const int guu = tid & 31;
    float bz = 0.f, br = 0.f, bh = 0.f;
    if (tid < 256) {
        bz = rb[u0 + guu];
        br = rb[U_ + u0 + guu];
        bh = rb[2 * U_ + u0 + guu];
    }

    unsigned* myc = cnt + (dir * 8 + bblk) * 32;   // private 128B line per group

    for (int s = 0; s < T_; s++) {
        const int t = dir ? (T_ - 1 - s) : s;

        if (s == 0) {
            for (int i = tid; i < 256 * 8; i += 384) hs[i] = 0.f;
        } else {
            const int tp = dir ? (t + 1) : (t - 1);
            for (int i = tid; i < 512; i += 384) {
                int bb = i & 7, kf = i >> 3;
                float4 v;
                if (layer == 1) {
                    v = __ldcg((const float4*)&g_h1[((size_t)(b0 + bb) * T_ + tp) * (2 * U_) + dir * U_ + kf * 4]);
                } else {
                    v = __ldcg((const float4*)&g_hs2[(s - 1) & 1][dir][b0 + bb][kf * 4]);
                }
                hs[(kf * 4 + 0) * 8 + bb] = v.x;
                hs[(kf * 4 + 1) * 8 + bb] = v.y;
                hs[(kf * 4 + 2) * 8 + bb] = v.z;
                hs[(kf * 4 + 3) * 8 + bb] = v.w;
            }
        }

        float xz = 0.f, xr = 0.f, xh = 0.f;
        if (tid < 256) {
            const float* xwp = xw + ((size_t)(b0 + gb) * T_ + t) * G_;
            xz = __ldg(xwp + u0 + guu);
            xr = __ldg(xwp + U_ + u0 + guu);
            xh = __ldg(xwp + 2 * U_ + u0 + guu);
        }
        __syncthreads();

        {
            float a0 = 0.f, a1 = 0.f, a2 = 0.f, a3 = 0.f;
            const float* wp = wk + (kh * 128) * 96 + colT;
            const float* hp = hs + (kh * 128) * 8 + bg * 4;
#pragma unroll 8
            for (int k = 0; k < 128; k++) {
                float  w  = wp[k * 96];
                float4 h4 = *(const float4*)(hp + k * 8);
                a0 = fmaf(h4.x, w, a0);
                a1 = fmaf(h4.y, w, a1);
                a2 = fmaf(h4.z, w, a2);
                a3 = fmaf(h4.w, w, a3);
            }
            part[(kh * 8 + bg * 4 + 0) * 96 + colT] = a0;
            part[(kh * 8 + bg * 4 + 1) * 96 + colT] = a1;
            part[(kh * 8 + bg * 4 + 2) * 96 + colT] = a2;
            part[(kh * 8 + bg * 4 + 3) * 96 + colT] = a3;
        }
        __syncthreads();

        if (tid < 256) {
            float az = bz + part[(0 * 8 + gb) * 96 + guu]      + part[(1 * 8 + gb) * 96 + guu];
            float ar = br + part[(0 * 8 + gb) * 96 + 32 + guu] + part[(1 * 8 + gb) * 96 + 32 + guu];
            float ah = bh + part[(0 * 8 + gb) * 96 + 64 + guu] + part[(1 * 8 + gb) * 96 + 64 + guu];
            float hprev = hs[(u0 + guu) * 8 + gb];
            float z  = 1.f / (1.f + expf(-(xz + az)));
            float rg = 1.f / (1.f + expf(-(xr + ar)));
            float hh = tanhf(xh + rg * ah);
            float hn = z * hprev + (1.f - z) * hh;
            if (layer == 1) {
                __stcg(&g_h1[((size_t)(b0 + gb) * T_ + t) * (2 * U_) + dir * U_ + u0 + guu], hn);
            } else {
                __stcg(&g_hs2[s & 1][dir][b0 + gb][u0 + guu], hn);
                if (s == T_ - 1) g_h2[b0 + gb][dir * U_ + u0 + guu] = hn;
            }
        }

        // group barrier: single cumulative release fence by tid0
        if (s != T_ - 1) {
            __syncthreads();
            if (tid == 0) {
                __threadfence();                       // release (cumulative)
                atomicAdd(myc, 1u);
                const unsigned target = 8u * (unsigned)(s + 1);
                while (*(volatile unsigned*)myc < target) { }
                __threadfence();                       // acquire
            }
            __syncthreads();
        }
    }
}

// ---------------- head: softmax(h2 @ wout + bout) ----------------
__global__ void head_k(const float* __restrict__ wout, const float* __restrict__ bout,
                       float* __restrict__ out)
{
    const int b = blockIdx.x, lane = threadIdx.x;
    float acc = 0.f;
    if (lane < C_) {
        acc = bout[lane];
        for (int k = 0; k < 2 * U_; k++)
            acc = fmaf(g_h2[b][k], wout[k * C_ + lane], acc);
    }
    float v = (lane < C_) ? acc : -INFINITY;
    for (int o = 16; o; o >>= 1) v = fmaxf(v, __shfl_xor_sync(0xffffffffu, v, o));
    float e = (lane < C_) ? expf(acc - v) : 0.f;
    float ssum = e;
    for (int o = 16; o; o >>= 1) ssum += __shfl_xor_sync(0xffffffffu, ssum, o);
    if (lane < C_) out[b * C_ + lane] = e / ssum;
}

// ---------------- launch ----------------
extern "C" void kernel_launch(void* const* d_in, const int* in_sizes, int n_in,
                              void* d_out, int out_size)
{
    const int*   x    = (const int*)  d_in[0];
    const float* emb  = (const float*)d_in[1];
    const float* k1f  = (const float*)d_in[2];
    const float* rk1f = (const float*)d_in[3];
    const float* b1f  = (const float*)d_in[4];
    const float* k1b  = (const float*)d_in[5];
    const float* rk1b = (const float*)d_in[6];
    const float* b1b  = (const float*)d_in[7];
    const float* k2f  = (const float*)d_in[8];
    const float* rk2f = (const float*)d_in[9];
    const float* b2f  = (const float*)d_in[10];
    const float* k2b  = (const float*)d_in[11];
    const float* rk2b = (const float*)d_in[12];
    const float* b2b  = (const float*)d_in[13];
    const float* wout = (const float*)d_in[14];
    const float* bout = (const float*)d_in[15];
    float* out = (float*)d_out;

    float *pxw0, *pxw1, *ph1;
    unsigned *pc1, *pc2;
    cudaGetSymbolAddress((void**)&pxw0, g_xw);
    pxw1 = pxw0 + (size_t)M_ * G_;
    cudaGetSymbolAddress((void**)&ph1,  g_h1);
    cudaGetSymbolAddress((void**)&pc1,  g_cnt1);
    cudaGetSymbolAddress((void**)&pc2,  g_cnt2);

    const int scan_smem = SC_SMEM_FLOATS * (int)sizeof(float);
    cudaFuncSetAttribute(scan_k,     cudaFuncAttributeMaxDynamicSharedMemorySize, scan_smem);
    cudaFuncSetAttribute(mma_gemm_k, cudaFuncAttributeMaxDynamicSharedMemorySize, GEMM_SMEM);

    dim3 gg(G_ / 128, M_ / 128);   // (6, 256)

    // 0) reset barrier counters
    init_k<<<1, 32>>>();

    // 1) layer-1 input projections, gather fused (A rows = emb[x[row]])
    mma_gemm_k<<<gg, 256, GEMM_SMEM>>>(emb, k1f, b1f, pxw0, E_, x);
    mma_gemm_k<<<gg, 256, GEMM_SMEM>>>(emb, k1b, b1b, pxw1, E_, x);

    // 2) layer-1 bidirectional scan -> g_h1
    scan_k<<<128, 384, scan_smem>>>(rk1f, b1f + G_, rk1b, b1b + G_, pc1, 1);

    // 3) layer-2 input projections
    mma_gemm_k<<<gg, 256, GEMM_SMEM>>>(ph1, k2f, b2f, pxw0, 2 * U_, (const int*)nullptr);
    mma_gemm_k<<<gg, 256, GEMM_SMEM>>>(ph1, k2b, b2b, pxw1, 2 * U_, (const int*)nullptr);

    // 4) layer-2 bidirectional scan -> g_h2
    scan_k<<<128, 384, scan_smem>>>(rk2f, b2f + G_, rk2b, b2b + G_, pc2, 2);

    // 5) output head
    head_k<<<B_, 32>>>(wout, bout, out);
}

// round 11
// speedup vs baseline: 2.5392x; 1.4618x over previous
#include <cuda_runtime.h>
#include <math.h>
#include <stdint.h>

// Problem constants
#define V_ 50000
#define E_ 300
#define T_ 512
#define U_ 256
#define G_ 768      // 3*U
#define B_ 64
#define C_ 20
#define M_ (B_*T_)  // 32768

// ---------------- static device scratch ----------------
__device__ float g_xw[2][(size_t)M_ * G_];     // input projections per direction
__device__ float g_h1[(size_t)M_ * 2 * U_];    // layer1 output [B,T,512]
__device__ float g_hs2[2][2][B_][U_];          // layer2 h double buffer [parity][dir][B][U]
__device__ float g_h2[B_][2 * U_];             // final states
__device__ unsigned g_cnt1[16 * 32];           // padded group counters
__device__ unsigned g_cnt2[16 * 32];

__device__ __forceinline__ uint32_t smem_u32(const void* p) {
    uint32_t a;
    asm("{ .reg .u64 t; cvta.to.shared.u64 t, %1; cvt.u32.u64 %0, t; }" : "=r"(a) : "l"(p));
    return a;
}
__device__ __forceinline__ void mma_tf32_16n8k8(float* c, const uint32_t* a, const uint32_t* b) {
    asm volatile(
        "mma.sync.aligned.m16n8k8.row.col.f32.tf32.tf32.f32 "
        "{%0,%1,%2,%3}, {%4,%5,%6,%7}, {%8,%9}, {%0,%1,%2,%3};"
        : "+f"(c[0]), "+f"(c[1]), "+f"(c[2]), "+f"(c[3])
        : "r"(a[0]), "r"(a[1]), "r"(a[2]), "r"(a[3]), "r"(b[0]), "r"(b[1]));
}
#define CP_COMMIT() asm volatile("cp.async.commit_group;" ::: "memory")
#define CP_WAIT(n)  asm volatile("cp.async.wait_group %0;" :: "n"(n) : "memory")

// ---------------- init: reset barrier counters ----------------
__global__ void init_k() {
    if (threadIdx.x < 16) {
        g_cnt1[threadIdx.x * 32] = 0u;
        g_cnt2[threadIdx.x * 32] = 0u;
    }
}

// ---------------- tf32 mma.sync GEMM, cp.async double-buffered (unchanged) ----------------
#define SA_ 36
#define SB_ 136
#define A_FLOATS (128 * SA_)
#define B_FLOATS (32 * SB_)
#define BUF_FLOATS (A_FLOATS + B_FLOATS)
#define GEMM_SMEM (2 * BUF_FLOATS * 4)

__device__ __forceinline__ void stage_tile(
    uint32_t sa, uint32_t sb, const float* __restrict__ arow_p,
    const float* __restrict__ W, int n0, int k0, int Kreal, int tid)
{
    {
        int arow  = tid >> 1;
        int aseg0 = (tid & 1) * 4;
#pragma unroll
        for (int q = 0; q < 4; q++) {
            int col = k0 + (aseg0 + q) * 4;
            int szf = Kreal - col; szf = szf < 0 ? 0 : (szf > 4 ? 4 : szf);
            int sz = szf * 4;
            const float* src = arow_p + (sz ? col : 0);
            uint32_t dst = sa + (uint32_t)(arow * SA_ + (aseg0 + q) * 4) * 4u;
            asm volatile("cp.async.cg.shared.global [%0], [%1], 16, %2;"
                         :: "r"(dst), "l"(src), "r"(sz) : "memory");
        }
    }
    {
        int krow  = tid >> 3;
        int bseg0 = (tid & 7) * 4;
        int kr = k0 + krow;
        int sz = (kr < Kreal) ? 16 : 0;
        const float* brow_p = W + (size_t)(sz ? kr : 0) * G_ + n0;
#pragma unroll
        for (int q = 0; q < 4; q++) {
            uint32_t dst = sb + (uint32_t)(krow * SB_ + (bseg0 + q) * 4) * 4u;
            asm volatile("cp.async.cg.shared.global [%0], [%1], 16, %2;"
                         :: "r"(dst), "l"(brow_p + (bseg0 + q) * 4), "r"(sz) : "memory");
        }
    }
}

__global__ void __launch_bounds__(256, 2) mma_gemm_k(
    const float* __restrict__ A, const float* __restrict__ W,
    const float* __restrict__ bias, float* __restrict__ Cc,
    int Kreal, const int* __restrict__ xidx)
{
    extern __shared__ float smf[];
    const uint32_t sbase = smem_u32(smf);

    const int tid  = threadIdx.x;
    const int wid  = tid >> 5;
    const int lane = tid & 31;
    const int lq   = lane & 3;
    const int gid  = lane >> 2;
    const int m0 = blockIdx.y * 128;
    const int n0 = blockIdx.x * 128;
    const int m0w = (wid & 3) * 32;
    const int n0w = (wid >> 2) * 64;

    const int arow = tid >> 1;
    const int ridx = xidx ? __ldg(&xidx[m0 + arow]) : (m0 + arow);
    const float* arow_p = A + (size_t)ridx * Kreal;

    float2 bv[8];
#pragma unroll
    for (int nt = 0; nt < 8; nt++)
        bv[nt] = *(const float2*)&bias[n0 + n0w + nt * 8 + lq * 2];

    float cfr[2][8][4];
#pragma unroll
    for (int mt = 0; mt < 2; mt++)
#pragma unroll
        for (int nt = 0; nt < 8; nt++)
#pragma unroll
            for (int j = 0; j < 4; j++) cfr[mt][nt][j] = 0.f;

    const int KT = (Kreal + 31) >> 5;

    stage_tile(sbase, sbase + A_FLOATS * 4u, arow_p, W, n0, 0, Kreal, tid);
    CP_COMMIT();

    for (int kt = 0; kt < KT; kt++) {
        const int cur = kt & 1;
        if (kt + 1 < KT) {
            uint32_t nb = sbase + (uint32_t)(((kt + 1) & 1) * BUF_FLOATS) * 4u;
            stage_tile(nb, nb + A_FLOATS * 4u, arow_p, W, n0, (kt + 1) << 5, Kreal, tid);
            CP_COMMIT();
            CP_WAIT(1);
        } else {
            CP_WAIT(0);
        }
        __syncthreads();

        const float* As_ = smf + cur * BUF_FLOATS;
        const float* Bs_ = As_ + A_FLOATS;

#pragma unroll
        for (int ks = 0; ks < 4; ks++) {
            const int kb = ks * 8;
            uint32_t af[2][4], bf[8][2];
#pragma unroll
            for (int mt = 0; mt < 2; mt++) {
                const float* ap = As_ + (m0w + mt * 16 + gid) * SA_ + kb + lq;
                af[mt][0] = __float_as_uint(ap[0]);
                af[mt][1] = __float_as_uint(ap[8 * SA_]);
                af[mt][2] = __float_as_uint(ap[4]);
                af[mt][3] = __float_as_uint(ap[8 * SA_ + 4]);
            }
#pragma unroll
            for (int nt = 0; nt < 8; nt++) {
                const float* bp = Bs_ + (kb + lq) * SB_ + n0w + nt * 8 + gid;
                bf[nt][0] = __float_as_uint(bp[0]);
                bf[nt][1] = __float_as_uint(bp[4 * SB_]);
            }
#pragma unroll
            for (int mt = 0; mt < 2; mt++)
#pragma unroll
                for (int nt = 0; nt < 8; nt++)
                    mma_tf32_16n8k8(cfr[mt][nt], af[mt], bf[nt]);
        }
        __syncthreads();
    }

#pragma unroll
    for (int mt = 0; mt < 2; mt++) {
        int row = m0 + m0w + mt * 16 + gid;
#pragma unroll
        for (int nt = 0; nt < 8; nt++) {
            int col = n0 + n0w + nt * 8 + lq * 2;
            float2 v0, v1;
            v0.x = cfr[mt][nt][0] + bv[nt].x;
            v0.y = cfr[mt][nt][1] + bv[nt].y;
            v1.x = cfr[mt][nt][2] + bv[nt].x;
            v1.y = cfr[mt][nt][3] + bv[nt].y;
            *(float2*)&Cc[(size_t)row * G_ + col] = v0;
            *(float2*)&Cc[(size_t)(row + 8) * G_ + col] = v1;
        }
    }
}

// ---------------- persistent bidirectional GRU scan — tensor-core dot ----------------
// grid = 64 CTAs: dir(2) x bblk(4, 16 batches) x ublk(8, 32 units). block = 512 (16 warps).
// Warp (kg = wid&3: 64-k slice, ng = wid>>2: 24-col slice) computes its partial
// h[16,64k] @ rk[64k, 24n] with m16n8k8 tf32 mma; recurrent weights held in REGISTERS.
// h exchanged via L2 (stcg/ldcg) with per-group monotonic counters.
#define HS_STRIDE 260
#define PT_STRIDE 100
__global__ void __launch_bounds__(512, 1) scan_k(
    const float* __restrict__ rkf, const float* __restrict__ rbf,
    const float* __restrict__ rkb, const float* __restrict__ rbb,
    unsigned* __restrict__ cnt, int layer)
{
    __shared__ float hs[16 * HS_STRIDE];             // h_prev [16 batches][256k + pad]
    __shared__ float part[4 * 16 * PT_STRIDE];       // [kg][16 m][96 cols + pad]

    const int cta  = blockIdx.x;
    const int dir  = cta >> 5;              // 0..1
    const int bblk = (cta >> 3) & 3;        // 0..3 (16 batches each)
    const int ublk = cta & 7;               // 0..7 (32 units each)
    const int b0 = bblk * 16, u0 = ublk * 32;
    const int tid  = threadIdx.x;
    const int wid  = tid >> 5;
    const int lane = tid & 31;
    const int lq   = lane & 3;
    const int gid  = lane >> 2;
    const int kg   = wid & 3;               // k-group: k in [kg*64, kg*64+64)
    const int ng   = wid >> 2;              // n-group: cols [ng*24, ng*24+24)

    const float* rk = dir ? rkb : rkf;
    const float* rb = dir ? rbb : rbf;
    const float* xw = g_xw[dir];

    // ---- load recurrent-weight B fragments into registers (once) ----
    // mma ntile nt: local col c = ng*24 + nt*8 + gid -> (gate g = c/32, unit uu = c%32)
    // b0 = rk[(kbase + lq)*G + ncol], b1 = rk[(kbase + lq + 4)*G + ncol]
    uint32_t bw[3][8][2];
#pragma unroll
    for (int nt = 0; nt < 3; nt++) {
        int c = ng * 24 + nt * 8 + gid;
        int ncol = (c >> 5) * U_ + u0 + (c & 31);
#pragma unroll
        for (int kt = 0; kt < 8; kt++) {
            int kb = kg * 64 + kt * 8 + lq;
            bw[nt][kt][0] = __float_as_uint(__ldg(&rk[(size_t)kb * G_ + ncol]));
            bw[nt][kt][1] = __float_as_uint(__ldg(&rk[(size_t)(kb + 4) * G_ + ncol]));
        }
    }

    // gate-phase role: thread -> (batch b = wid, unit uu = lane)
    const int gb  = wid;                    // 0..15
    const int guu = lane;                   // 0..31
    const float bz = rb[u0 + guu];
    const float brr = rb[U_ + u0 + guu];
    const float bh = rb[2 * U_ + u0 + guu];

    unsigned* myc = cnt + (dir * 4 + bblk) * 32;   // private 128B line per group

    for (int s = 0; s < T_; s++) {
        const int t = dir ? (T_ - 1 - s) : s;

        // ---- stage prev h into hs[b][k] ----
        if (s == 0) {
            for (int i = tid; i < 16 * HS_STRIDE; i += 512) hs[i] = 0.f;
        } else {
            const int tp = dir ? (t + 1) : (t - 1);
#pragma unroll
            for (int q = 0; q < 2; q++) {
                int idx = tid + q * 512;            // 0..1023
                int bb = idx >> 6, kf = idx & 63;
                float4 v;
                if (layer == 1) {
                    v = __ldcg((const float4*)&g_h1[((size_t)(b0 + bb) * T_ + tp) * (2 * U_) + dir * U_ + kf * 4]);
                } else {
                    v = __ldcg((const float4*)&g_hs2[(s - 1) & 1][dir][b0 + bb][kf * 4]);
                }
                *(float4*)&hs[bb * HS_STRIDE + kf * 4] = v;
            }
        }

        // prefetch xw for gate phase (latency hidden under dot)
        const float* xwp = xw + ((size_t)(b0 + gb) * T_ + t) * G_;
        float xz = __ldg(xwp + u0 + guu);
        float xr = __ldg(xwp + U_ + u0 + guu);
        float xh = __ldg(xwp + 2 * U_ + u0 + guu);
        __syncthreads();

        // ---- tensor-core partial dot: h[16, kg-slice] @ rk[kg-slice, ng-cols] ----
        {
            float acc[3][4];
#pragma unroll
            for (int nt = 0; nt < 3; nt++)
#pragma unroll
                for (int j = 0; j < 4; j++) acc[nt][j] = 0.f;

#pragma unroll
            for (int kt = 0; kt < 8; kt++) {
                const int kb = kg * 64 + kt * 8;
                uint32_t af[4];
                af[0] = __float_as_uint(hs[gid * HS_STRIDE + kb + lq]);
                af[1] = __float_as_uint(hs[(gid + 8) * HS_STRIDE + kb + lq]);
                af[2] = __float_as_uint(hs[gid * HS_STRIDE + kb + lq + 4]);
                af[3] = __float_as_uint(hs[(gid + 8) * HS_STRIDE + kb + lq + 4]);
#pragma unroll
                for (int nt = 0; nt < 3; nt++)
                    mma_tf32_16n8k8(acc[nt], af, bw[nt][kt]);
            }

            float* pp = part + kg * (16 * PT_STRIDE);
#pragma unroll
            for (int nt = 0; nt < 3; nt++) {
                int colb = ng * 24 + nt * 8 + 2 * lq;
                *(float2*)&pp[gid * PT_STRIDE + colb]       = make_float2(acc[nt][0], acc[nt][1]);
                *(float2*)&pp[(gid + 8) * PT_STRIDE + colb] = make_float2(acc[nt][2], acc[nt][3]);
            }
        }
        __syncthreads();

        // ---- gates: thread (gb, guu) ----
        {
            float az = bz, ar = brr, ah = bh;
#pragma unroll
            for (int k4 = 0; k4 < 4; k4++) {
                const float* pp = part + k4 * (16 * PT_STRIDE) + gb * PT_STRIDE;
                az += pp[guu];
                ar += pp[32 + guu];
                ah += pp[64 + guu];
            }
            float hprev = hs[gb * HS_STRIDE + u0 + guu];
            float z  = 1.f / (1.f + expf(-(xz + az)));
            float rg = 1.f / (1.f + expf(-(xr + ar)));
            float hh = tanhf(xh + rg * ah);
            float hn = z * hprev + (1.f - z) * hh;
            if (layer == 1) {
                __stcg(&g_h1[((size_t)(b0 + gb) * T_ + t) * (2 * U_) + dir * U_ + u0 + guu], hn);
            } else {
                __stcg(&g_hs2[s & 1][dir][b0 + gb][u0 + guu], hn);
                if (s == T_ - 1) g_h2[b0 + gb][dir * U_ + u0 + guu] = hn;
            }
        }

        // ---- group barrier (8 CTAs sharing (dir, bblk)) ----
        if (s != T_ - 1) {
            __syncthreads();
            if (tid == 0) {
                __threadfence();                       // release (cumulative)
                atomicAdd(myc, 1u);
                const unsigned target = 8u * (unsigned)(s + 1);
                while (*(volatile unsigned*)myc < target) { }
                __threadfence();                       // acquire
            }
            __syncthreads();
        }
    }
}

// ---------------- head: softmax(h2 @ wout + bout) ----------------
__global__ void head_k(const float* __restrict__ wout, const float* __restrict__ bout,
                       float* __restrict__ out)
{
    const int b = blockIdx.x, lane = threadIdx.x;
    float acc = 0.f;
    if (lane < C_) {
        acc = bout[lane];
        for (int k = 0; k < 2 * U_; k++)
            acc = fmaf(g_h2[b][k], wout[k * C_ + lane], acc);
    }
    float v = (lane < C_) ? acc : -INFINITY;
    for (int o = 16; o; o >>= 1) v = fmaxf(v, __shfl_xor_sync(0xffffffffu, v, o));
    float e = (lane < C_) ? expf(acc - v) : 0.f;
    float ssum = e;
    for (int o = 16; o; o >>= 1) ssum += __shfl_xor_sync(0xffffffffu, ssum, o);
    if (lane < C_) out[b * C_ + lane] = e / ssum;
}

// ---------------- launch ----------------
extern "C" void kernel_launch(void* const* d_in, const int* in_sizes, int n_in,
                              void* d_out, int out_size)
{
    const int*   x    = (const int*)  d_in[0];
    const float* emb  = (const float*)d_in[1];
    const float* k1f  = (const float*)d_in[2];
    const float* rk1f = (const float*)d_in[3];
    const float* b1f  = (const float*)d_in[4];
    const float* k1b  = (const float*)d_in[5];
    const float* rk1b = (const float*)d_in[6];
    const float* b1b  = (const float*)d_in[7];
    const float* k2f  = (const float*)d_in[8];
    const float* rk2f = (const float*)d_in[9];
    const float* b2f  = (const float*)d_in[10];
    const float* k2b  = (const float*)d_in[11];
    const float* rk2b = (const float*)d_in[12];
    const float* b2b  = (const float*)d_in[13];
    const float* wout = (const float*)d_in[14];
    const float* bout = (const float*)d_in[15];
    float* out = (float*)d_out;

    float *pxw0, *pxw1, *ph1;
    unsigned *pc1, *pc2;
    cudaGetSymbolAddress((void**)&pxw0, g_xw);
    pxw1 = pxw0 + (size_t)M_ * G_;
    cudaGetSymbolAddress((void**)&ph1,  g_h1);
    cudaGetSymbolAddress((void**)&pc1,  g_cnt1);
    cudaGetSymbolAddress((void**)&pc2,  g_cnt2);

    cudaFuncSetAttribute(mma_gemm_k, cudaFuncAttributeMaxDynamicSharedMemorySize, GEMM_SMEM);

    dim3 gg(G_ / 128, M_ / 128);   // (6, 256)

    // 0) reset barrier counters
    init_k<<<1, 32>>>();

    // 1) layer-1 input projections, gather fused (A rows = emb[x[row]])
    mma_gemm_k<<<gg, 256, GEMM_SMEM>>>(emb, k1f, b1f, pxw0, E_, x);
    mma_gemm_k<<<gg, 256, GEMM_SMEM>>>(emb, k1b, b1b, pxw1, E_, x);

    // 2) layer-1 bidirectional scan -> g_h1  (tensor-core dot)
    scan_k<<<64, 512>>>(rk1f, b1f + G_, rk1b, b1b + G_, pc1, 1);

    // 3) layer-2 input projections
    mma_gemm_k<<<gg, 256, GEMM_SMEM>>>(ph1, k2f, b2f, pxw0, 2 * U_, (const int*)nullptr);
    mma_gemm_k<<<gg, 256, GEMM_SMEM>>>(ph1, k2b, b2b, pxw1, 2 * U_, (const int*)nullptr);

    // 4) layer-2 bidirectional scan -> g_h2
    scan_k<<<64, 512>>>(rk2f, b2f + G_, rk2b, b2b + G_, pc2, 2);

    // 5) output head
    head_k<<<B_, 32>>>(wout, bout, out);
}